// round 4
// baseline (speedup 1.0000x reference)
#include <cuda_runtime.h>
#include <cuda_bf16.h>
#include <mma.h>
#include <math.h>
#include <stdint.h>

using namespace nvcuda;

// Problem constants
#define BATCH 64
#define NATOM 512
#define DFEAT 128
#define DIMP  128
#define MROWS (BATCH * NATOM)      // 32768
#define NCOLS (2 * DIMP)           // 256 (Wq | Wk fused in n)

// Split-K GEMM: K = 384 = 3 segments of 128 (Ah*Bh + Al*Bh + Ah*Bl)
#define KTOT 384
#define GBK  32                    // k per stage
#define ASTRIDE 40                 // smem A tile col stride (32 + 8 pad)
#define BSTRIDE 136                // smem B tile col stride (128 + 8 pad)

// Device scratch (allocation-free rule)
__device__ __nv_bfloat16 g_Abf[(size_t)MROWS * 256];   // [Ah | Al], 16 MB
__device__ __nv_bfloat16 g_Bbf[(size_t)KTOT * NCOLS];  // [Bh; Bh; Bl], 192 KB
__device__ float g_bias[NCOLS];
__device__ float g_Q[(size_t)MROWS * DIMP];            // 16 MB
__device__ float g_K[(size_t)MROWS * DIMP];            // 16 MB

// ---------------------------------------------------------------------------
// convertA: fp32 A[32768,128] -> bf16 hi|lo [32768,256]
// ---------------------------------------------------------------------------
__global__ __launch_bounds__(512)
void convertA_kernel(const float* __restrict__ A) {
    int idx = blockIdx.x * blockDim.x + threadIdx.x;   // < 32768*32
    int m  = idx >> 5;
    int d4 = (idx & 31) << 2;
    float4 a = *(const float4*)(A + (size_t)m * DFEAT + d4);

    float v[4] = {a.x, a.y, a.z, a.w};
    uint16_t h[4], l[4];
    #pragma unroll
    for (int i = 0; i < 4; i++) {
        __nv_bfloat16 hb = __float2bfloat16(v[i]);
        __nv_bfloat16 lb = __float2bfloat16(v[i] - __bfloat162float(hb));
        h[i] = __bfloat16_as_ushort(hb);
        l[i] = __bfloat16_as_ushort(lb);
    }
    uint2 hp = make_uint2(((uint32_t)h[1] << 16) | h[0], ((uint32_t)h[3] << 16) | h[2]);
    uint2 lp = make_uint2(((uint32_t)l[1] << 16) | l[0], ((uint32_t)l[3] << 16) | l[2]);

    *(uint2*)(g_Abf + (size_t)m * 256 + d4)       = hp;
    *(uint2*)(g_Abf + (size_t)m * 256 + 128 + d4) = lp;
}

// ---------------------------------------------------------------------------
// convertB: Wq|Wk [128,128] fp32 -> g_Bbf [384,256] bf16 = [Bh; Bh; Bl]; bias.
// ---------------------------------------------------------------------------
__global__ __launch_bounds__(256)
void convertB_kernel(const float* __restrict__ Wq, const float* __restrict__ Wk,
                     const float* __restrict__ bq, const float* __restrict__ bk) {
    int idx = blockIdx.x * blockDim.x + threadIdx.x;   // < 8192
    int k  = idx >> 6;
    int n4 = (idx & 63) << 2;

    float4 w = (n4 < DIMP)
        ? *(const float4*)(Wq + (size_t)k * DIMP + n4)
        : *(const float4*)(Wk + (size_t)k * DIMP + (n4 - DIMP));

    float v[4] = {w.x, w.y, w.z, w.w};
    uint16_t h[4], l[4];
    #pragma unroll
    for (int i = 0; i < 4; i++) {
        __nv_bfloat16 hb = __float2bfloat16(v[i]);
        __nv_bfloat16 lb = __float2bfloat16(v[i] - __bfloat162float(hb));
        h[i] = __bfloat16_as_ushort(hb);
        l[i] = __bfloat16_as_ushort(lb);
    }
    uint2 hp = make_uint2(((uint32_t)h[1] << 16) | h[0], ((uint32_t)h[3] << 16) | h[2]);
    uint2 lp = make_uint2(((uint32_t)l[1] << 16) | l[0], ((uint32_t)l[3] << 16) | l[2]);

    *(uint2*)(g_Bbf + (size_t)k * NCOLS + n4)         = hp;
    *(uint2*)(g_Bbf + (size_t)(128 + k) * NCOLS + n4) = hp;
    *(uint2*)(g_Bbf + (size_t)(256 + k) * NCOLS + n4) = lp;

    if (idx < DIMP) { g_bias[idx] = bq[idx]; g_bias[DIMP + idx] = bk[idx]; }
}

// ---------------------------------------------------------------------------
// wmma GEMM: grid (256, 2). CTA = 128m x 128n, K=384. 8 warps, 64x32 per warp.
// Double-buffered smem staging (k=32 per stage). Bias pre-loaded into acc.
// ---------------------------------------------------------------------------
__global__ __launch_bounds__(256, 2)
void wmma_gemm_kernel() {
    __shared__ __nv_bfloat16 A_s[2][128 * ASTRIDE];   // 20480 B
    __shared__ __nv_bfloat16 B_s[2][GBK * BSTRIDE];   // 17408 B
    __shared__ float biasT[16 * 128];                 // 8192 B

    const int tid  = threadIdx.x;
    const int warp = tid >> 5;
    const int bm   = blockIdx.x * 128;
    const int bn   = blockIdx.y * 128;
    const int wm   = (warp >> 2) * 64;
    const int wn   = (warp & 3) * 32;

    // replicated bias tile (16 identical rows) for accumulator init
    for (int i = tid; i < 16 * 128; i += 256) biasT[i] = g_bias[bn + (i & 127)];

    // loader lanes: each thread moves 2 float4 (16 bf16) for A and for B
    const int f0 = tid * 2, f1 = tid * 2 + 1;
    const int ar0 = f0 >> 2, ac0 = (f0 & 3) * 8;
    const int ar1 = f1 >> 2, ac1 = (f1 & 3) * 8;
    const int br0 = f0 >> 4, bc0 = (f0 & 15) * 8;
    const int br1 = f1 >> 4, bc1 = (f1 & 15) * 8;

    wmma::fragment<wmma::accumulator, 16, 16, 16, float> acc[4][2];
    __syncthreads();
    #pragma unroll
    for (int i = 0; i < 4; i++)
        #pragma unroll
        for (int j = 0; j < 2; j++)
            wmma::load_matrix_sync(acc[i][j], biasT + wn + j * 16, 128, wmma::mem_row_major);

    uint4 ra0, ra1, rb0, rb1;
    // fetch stage for iteration `it` into registers
    #define FETCH(it)                                                                     \
        do {                                                                              \
            int seg_ = (it) >> 2, kin_ = ((it) & 3) * GBK;                                \
            int acol_ = ((seg_ == 1) ? 128 : 0) + kin_;                                   \
            ra0 = *(const uint4*)(g_Abf + (size_t)(bm + ar0) * 256 + acol_ + ac0);        \
            ra1 = *(const uint4*)(g_Abf + (size_t)(bm + ar1) * 256 + acol_ + ac1);        \
            rb0 = *(const uint4*)(g_Bbf + (size_t)((it) * GBK + br0) * NCOLS + bn + bc0); \
            rb1 = *(const uint4*)(g_Bbf + (size_t)((it) * GBK + br1) * NCOLS + bn + bc1); \
        } while (0)
    #define STORE(buf)                                                \
        do {                                                          \
            *(uint4*)(&A_s[buf][ar0 * ASTRIDE + ac0]) = ra0;          \
            *(uint4*)(&A_s[buf][ar1 * ASTRIDE + ac1]) = ra1;          \
            *(uint4*)(&B_s[buf][br0 * BSTRIDE + bc0]) = rb0;          \
            *(uint4*)(&B_s[buf][br1 * BSTRIDE + bc1]) = rb1;          \
        } while (0)

    FETCH(0);
    STORE(0);
    __syncthreads();

    const int NIT = KTOT / GBK;   // 12
    for (int it = 0; it < NIT; it++) {
        const int cur = it & 1;
        if (it < NIT - 1) FETCH(it + 1);

        #pragma unroll
        for (int kk = 0; kk < GBK; kk += 16) {
            wmma::fragment<wmma::matrix_a, 16, 16, 16, __nv_bfloat16, wmma::row_major> af[4];
            wmma::fragment<wmma::matrix_b, 16, 16, 16, __nv_bfloat16, wmma::row_major> bf[2];
            #pragma unroll
            for (int i = 0; i < 4; i++)
                wmma::load_matrix_sync(af[i], &A_s[cur][(wm + i * 16) * ASTRIDE + kk], ASTRIDE);
            #pragma unroll
            for (int j = 0; j < 2; j++)
                wmma::load_matrix_sync(bf[j], &B_s[cur][kk * BSTRIDE + wn + j * 16], BSTRIDE);
            #pragma unroll
            for (int i = 0; i < 4; i++)
                #pragma unroll
                for (int j = 0; j < 2; j++)
                    wmma::mma_sync(acc[i][j], af[i], bf[j], acc[i][j]);
        }

        if (it < NIT - 1) {
            STORE(1 - cur);
            __syncthreads();
        }
    }

    // epilogue: n-tile 0 -> Q, n-tile 1 -> K (each 128 wide, ld = DIMP)
    float* dst = (blockIdx.y == 0) ? g_Q : g_K;
    #pragma unroll
    for (int i = 0; i < 4; i++) {
        const size_t row = (size_t)(bm + wm + i * 16);
        #pragma unroll
        for (int j = 0; j < 2; j++)
            wmma::store_matrix_sync(dst + row * DIMP + wn + j * 16, acc[i][j],
                                    DIMP, wmma::mem_row_major);
    }
    #undef FETCH
    #undef STORE
}

// ---------------------------------------------------------------------------
// Block reductions (512 threads, 16 warps)
// ---------------------------------------------------------------------------
__device__ __forceinline__ float block_reduce_sum(float v, float* red) {
    int lane = threadIdx.x & 31, warp = threadIdx.x >> 5;
    #pragma unroll
    for (int o = 16; o; o >>= 1) v += __shfl_down_sync(0xffffffffu, v, o);
    if (lane == 0) red[warp] = v;
    __syncthreads();
    if (warp == 0) {
        v = (lane < 16) ? red[lane] : 0.0f;
        #pragma unroll
        for (int o = 8; o; o >>= 1) v += __shfl_down_sync(0xffffffffu, v, o);
        if (lane == 0) red[16] = v;
    }
    __syncthreads();
    float r = red[16];
    __syncthreads();
    return r;
}

__device__ __forceinline__ float block_reduce_max(float v, float* red) {
    int lane = threadIdx.x & 31, warp = threadIdx.x >> 5;
    #pragma unroll
    for (int o = 16; o; o >>= 1) v = fmaxf(v, __shfl_down_sync(0xffffffffu, v, o));
    if (lane == 0) red[warp] = v;
    __syncthreads();
    if (warp == 0) {
        v = (lane < 16) ? red[lane] : -INFINITY;
        #pragma unroll
        for (int o = 8; o; o >>= 1) v = fmaxf(v, __shfl_down_sync(0xffffffffu, v, o));
        if (lane == 0) red[16] = v;
    }
    __syncthreads();
    float r = red[16];
    __syncthreads();
    return r;
}

// ---------------------------------------------------------------------------
// Per-batch epilogue: q_sum -> agg -> normalize -> masked softmax -> context
// ---------------------------------------------------------------------------
__global__ __launch_bounds__(512)
void attn_kernel(const float* __restrict__ mask, float* __restrict__ out) {
    const int b = blockIdx.x;
    const float* __restrict__ Kb = g_K + (size_t)b * NATOM * DIMP;
    const float* __restrict__ Qb = g_Q + (size_t)b * NATOM * DIMP;
    const float* __restrict__ m  = mask + (size_t)b * NATOM;

    __shared__ float qsum[DIMP];
    __shared__ float aggS[NATOM];
    __shared__ float attnS[NATOM];
    __shared__ float part4[4][DIMP];
    __shared__ float red[17];

    const int tid  = threadIdx.x;
    const int lane = tid & 31, warp = tid >> 5;
    const int d = tid & 127, p = tid >> 7;

    // --- q_sum[d] = sum_n mask[n]*q[n][d] ---
    {
        float acc = 0.0f;
        const int n0 = p * 128;
        #pragma unroll 4
        for (int n = n0; n < n0 + 128; n++)
            acc += m[n] * Qb[(size_t)n * DIMP + d];
        part4[p][d] = acc;
    }
    __syncthreads();
    if (tid < DIMP) qsum[tid] = part4[0][tid] + part4[1][tid] + part4[2][tid] + part4[3][tid];
    __syncthreads();

    // --- agg[n] = mask[n] * (k[n].q_sum - k[n].q[n]) ---
    for (int r = 0; r < 32; r++) {
        const int n = warp * 32 + r;
        const float* kr = Kb + (size_t)n * DIMP;
        const float* qr = Qb + (size_t)n * DIMP;
        float s1 = 0.0f, s2 = 0.0f;
        #pragma unroll
        for (int dd = lane; dd < DIMP; dd += 32) {
            float kv = kr[dd];
            s1 += kv * qsum[dd];
            s2 += kv * qr[dd];
        }
        #pragma unroll
        for (int o = 16; o; o >>= 1) {
            s1 += __shfl_down_sync(0xffffffffu, s1, o);
            s2 += __shfl_down_sync(0xffffffffu, s2, o);
        }
        if (lane == 0) aggS[n] = m[n] * (s1 - s2);
    }
    __syncthreads();

    // --- normalize over atoms, masked softmax ---
    const float v = aggS[tid];
    const float total = block_reduce_sum(v * v, red);
    const float nrm = sqrtf(total);
    const float x = v / nrm + (1.0f - m[tid]) * (-1e9f);
    const float mx = block_reduce_max(x, red);
    const float e = expf(x - mx);
    const float denom = block_reduce_sum(e, red);
    const float attn = e / denom;
    out[(size_t)b * NATOM + tid] = attn;
    attnS[tid] = attn * m[tid];
    __syncthreads();

    // --- context[d] = sum_n mask[n]*attn[n]*k[n][d] ---
    {
        float acc = 0.0f;
        const int n0 = p * 128;
        #pragma unroll 4
        for (int n = n0; n < n0 + 128; n++)
            acc += attnS[n] * Kb[(size_t)n * DIMP + d];
        part4[p][d] = acc;
    }
    __syncthreads();
    if (tid < DIMP)
        out[(size_t)BATCH * NATOM + (size_t)b * DIMP + tid] =
            part4[0][tid] + part4[1][tid] + part4[2][tid] + part4[3][tid];
}

// ---------------------------------------------------------------------------
extern "C" void kernel_launch(void* const* d_in, const int* in_sizes, int n_in,
                              void* d_out, int out_size) {
    const float* atom_query = (const float*)d_in[0];
    const float* mask       = (const float*)d_in[1];
    const float* Wq         = (const float*)d_in[2];
    const float* bq         = (const float*)d_in[3];
    const float* Wk         = (const float*)d_in[4];
    const float* bk         = (const float*)d_in[5];
    float* out = (float*)d_out;

    convertA_kernel<<<MROWS * 32 / 512, 512>>>(atom_query);
    convertB_kernel<<<32, 256>>>(Wq, Wk, bq, bk);
    wmma_gemm_kernel<<<dim3(MROWS / 128, 2), 256>>>();
    attn_kernel<<<BATCH, 512>>>(mask, out);
}

// round 5
// speedup vs baseline: 1.8195x; 1.8195x over previous
#include <cuda_runtime.h>
#include <cuda_bf16.h>
#include <mma.h>
#include <math.h>
#include <stdint.h>

using namespace nvcuda;

// Problem constants
#define BATCH 64
#define NATOM 512
#define DFEAT 128
#define DIMP  128
#define MROWS (BATCH * NATOM)      // 32768
#define NCOLS (2 * DIMP)           // 256 (Wq | Wk fused in n)
#define NSLICE 8                   // atom slices per batch (512/8 = 64 atoms)
#define SLATOM (NATOM / NSLICE)    // 64

// Split-K GEMM: K = 384 = 3 segments of 128 (Ah*Bh + Al*Bh + Ah*Bl)
#define KTOT 384
#define GBK  32                    // k per stage
#define ASTRIDE 40                 // smem A tile col stride (32 + 8 pad)
#define BSTRIDE 136                // smem B tile col stride (128 + 8 pad)

// Device scratch (allocation-free rule)
__device__ __nv_bfloat16 g_Abf[(size_t)MROWS * 256];   // [Ah | Al], 16 MB
__device__ __nv_bfloat16 g_Bbf[(size_t)KTOT * NCOLS];  // [Bh; Bh; Bl], 192 KB
__device__ float g_bias[NCOLS];
__device__ float g_Q[(size_t)MROWS * DIMP];            // 16 MB
__device__ float g_K[(size_t)MROWS * DIMP];            // 16 MB
__device__ float g_qsum_part[BATCH][NSLICE][DIMP];     // 256 KB
__device__ float g_agg[MROWS];                         // 128 KB
__device__ float g_attnW[MROWS];                       // 128 KB
__device__ float g_ctx_part[BATCH][NSLICE][DIMP];      // 256 KB

// ---------------------------------------------------------------------------
// convertA: fp32 A[32768,128] -> bf16 hi|lo [32768,256]
// ---------------------------------------------------------------------------
__global__ __launch_bounds__(512)
void convertA_kernel(const float* __restrict__ A) {
    int idx = blockIdx.x * blockDim.x + threadIdx.x;   // < 32768*32
    int m  = idx >> 5;
    int d4 = (idx & 31) << 2;
    float4 a = *(const float4*)(A + (size_t)m * DFEAT + d4);

    float v[4] = {a.x, a.y, a.z, a.w};
    uint16_t h[4], l[4];
    #pragma unroll
    for (int i = 0; i < 4; i++) {
        __nv_bfloat16 hb = __float2bfloat16(v[i]);
        __nv_bfloat16 lb = __float2bfloat16(v[i] - __bfloat162float(hb));
        h[i] = __bfloat16_as_ushort(hb);
        l[i] = __bfloat16_as_ushort(lb);
    }
    uint2 hp = make_uint2(((uint32_t)h[1] << 16) | h[0], ((uint32_t)h[3] << 16) | h[2]);
    uint2 lp = make_uint2(((uint32_t)l[1] << 16) | l[0], ((uint32_t)l[3] << 16) | l[2]);

    *(uint2*)(g_Abf + (size_t)m * 256 + d4)       = hp;
    *(uint2*)(g_Abf + (size_t)m * 256 + 128 + d4) = lp;
}

// ---------------------------------------------------------------------------
// convertB: Wq|Wk [128,128] fp32 -> g_Bbf [384,256] bf16 = [Bh; Bh; Bl]; bias.
// ---------------------------------------------------------------------------
__global__ __launch_bounds__(256)
void convertB_kernel(const float* __restrict__ Wq, const float* __restrict__ Wk,
                     const float* __restrict__ bq, const float* __restrict__ bk) {
    int idx = blockIdx.x * blockDim.x + threadIdx.x;   // < 8192
    int k  = idx >> 6;
    int n4 = (idx & 63) << 2;

    float4 w = (n4 < DIMP)
        ? *(const float4*)(Wq + (size_t)k * DIMP + n4)
        : *(const float4*)(Wk + (size_t)k * DIMP + (n4 - DIMP));

    float v[4] = {w.x, w.y, w.z, w.w};
    uint16_t h[4], l[4];
    #pragma unroll
    for (int i = 0; i < 4; i++) {
        __nv_bfloat16 hb = __float2bfloat16(v[i]);
        __nv_bfloat16 lb = __float2bfloat16(v[i] - __bfloat162float(hb));
        h[i] = __bfloat16_as_ushort(hb);
        l[i] = __bfloat16_as_ushort(lb);
    }
    uint2 hp = make_uint2(((uint32_t)h[1] << 16) | h[0], ((uint32_t)h[3] << 16) | h[2]);
    uint2 lp = make_uint2(((uint32_t)l[1] << 16) | l[0], ((uint32_t)l[3] << 16) | l[2]);

    *(uint2*)(g_Bbf + (size_t)k * NCOLS + n4)         = hp;
    *(uint2*)(g_Bbf + (size_t)(128 + k) * NCOLS + n4) = hp;
    *(uint2*)(g_Bbf + (size_t)(256 + k) * NCOLS + n4) = lp;

    if (idx < DIMP) { g_bias[idx] = bq[idx]; g_bias[DIMP + idx] = bk[idx]; }
}

// ---------------------------------------------------------------------------
// wmma GEMM: grid (256, 2). CTA = 128m x 128n, K=384. 8 warps, 64x32 per warp.
// ---------------------------------------------------------------------------
__global__ __launch_bounds__(256, 2)
void wmma_gemm_kernel() {
    __shared__ __nv_bfloat16 A_s[2][128 * ASTRIDE];   // 20480 B
    __shared__ __nv_bfloat16 B_s[2][GBK * BSTRIDE];   // 17408 B
    __shared__ float biasT[16 * 128];                 // 8192 B

    const int tid  = threadIdx.x;
    const int warp = tid >> 5;
    const int bm   = blockIdx.x * 128;
    const int bn   = blockIdx.y * 128;
    const int wm   = (warp >> 2) * 64;
    const int wn   = (warp & 3) * 32;

    for (int i = tid; i < 16 * 128; i += 256) biasT[i] = g_bias[bn + (i & 127)];

    const int f0 = tid * 2, f1 = tid * 2 + 1;
    const int ar0 = f0 >> 2, ac0 = (f0 & 3) * 8;
    const int ar1 = f1 >> 2, ac1 = (f1 & 3) * 8;
    const int br0 = f0 >> 4, bc0 = (f0 & 15) * 8;
    const int br1 = f1 >> 4, bc1 = (f1 & 15) * 8;

    wmma::fragment<wmma::accumulator, 16, 16, 16, float> acc[4][2];
    __syncthreads();
    #pragma unroll
    for (int i = 0; i < 4; i++)
        #pragma unroll
        for (int j = 0; j < 2; j++)
            wmma::load_matrix_sync(acc[i][j], biasT + wn + j * 16, 128, wmma::mem_row_major);

    uint4 ra0, ra1, rb0, rb1;
    #define FETCH(it)                                                                     \
        do {                                                                              \
            int seg_ = (it) >> 2, kin_ = ((it) & 3) * GBK;                                \
            int acol_ = ((seg_ == 1) ? 128 : 0) + kin_;                                   \
            ra0 = *(const uint4*)(g_Abf + (size_t)(bm + ar0) * 256 + acol_ + ac0);        \
            ra1 = *(const uint4*)(g_Abf + (size_t)(bm + ar1) * 256 + acol_ + ac1);        \
            rb0 = *(const uint4*)(g_Bbf + (size_t)((it) * GBK + br0) * NCOLS + bn + bc0); \
            rb1 = *(const uint4*)(g_Bbf + (size_t)((it) * GBK + br1) * NCOLS + bn + bc1); \
        } while (0)
    #define STORE(buf)                                                \
        do {                                                          \
            *(uint4*)(&A_s[buf][ar0 * ASTRIDE + ac0]) = ra0;          \
            *(uint4*)(&A_s[buf][ar1 * ASTRIDE + ac1]) = ra1;          \
            *(uint4*)(&B_s[buf][br0 * BSTRIDE + bc0]) = rb0;          \
            *(uint4*)(&B_s[buf][br1 * BSTRIDE + bc1]) = rb1;          \
        } while (0)

    FETCH(0);
    STORE(0);
    __syncthreads();

    const int NIT = KTOT / GBK;   // 12
    for (int it = 0; it < NIT; it++) {
        const int cur = it & 1;
        if (it < NIT - 1) FETCH(it + 1);

        #pragma unroll
        for (int kk = 0; kk < GBK; kk += 16) {
            wmma::fragment<wmma::matrix_a, 16, 16, 16, __nv_bfloat16, wmma::row_major> af[4];
            wmma::fragment<wmma::matrix_b, 16, 16, 16, __nv_bfloat16, wmma::row_major> bf[2];
            #pragma unroll
            for (int i = 0; i < 4; i++)
                wmma::load_matrix_sync(af[i], &A_s[cur][(wm + i * 16) * ASTRIDE + kk], ASTRIDE);
            #pragma unroll
            for (int j = 0; j < 2; j++)
                wmma::load_matrix_sync(bf[j], &B_s[cur][kk * BSTRIDE + wn + j * 16], BSTRIDE);
            #pragma unroll
            for (int i = 0; i < 4; i++)
                #pragma unroll
                for (int j = 0; j < 2; j++)
                    wmma::mma_sync(acc[i][j], af[i], bf[j], acc[i][j]);
        }

        if (it < NIT - 1) {
            STORE(1 - cur);
            __syncthreads();
        }
    }

    float* dst = (blockIdx.y == 0) ? g_Q : g_K;
    #pragma unroll
    for (int i = 0; i < 4; i++) {
        const size_t row = (size_t)(bm + wm + i * 16);
        #pragma unroll
        for (int j = 0; j < 2; j++)
            wmma::store_matrix_sync(dst + row * DIMP + wn + j * 16, acc[i][j],
                                    DIMP, wmma::mem_row_major);
    }
    #undef FETCH
    #undef STORE
}

// ---------------------------------------------------------------------------
// qsum_part: grid (BATCH, NSLICE), 256 threads. Partial masked colsum of Q.
// ---------------------------------------------------------------------------
__global__ __launch_bounds__(256)
void qsum_part_kernel(const float* __restrict__ mask) {
    const int b = blockIdx.x, s = blockIdx.y;
    const int d = threadIdx.x & 127, h = threadIdx.x >> 7;
    const float* __restrict__ Qb = g_Q + ((size_t)b * NATOM + s * SLATOM) * DIMP;
    const float* __restrict__ m  = mask + (size_t)b * NATOM + s * SLATOM;

    __shared__ float part[2][DIMP];
    float acc = 0.0f;
    const int n0 = h * (SLATOM / 2);
    #pragma unroll 4
    for (int n = n0; n < n0 + SLATOM / 2; n++)
        acc += m[n] * Qb[(size_t)n * DIMP + d];
    part[h][d] = acc;
    __syncthreads();
    if (threadIdx.x < DIMP)
        g_qsum_part[b][s][threadIdx.x] = part[0][threadIdx.x] + part[1][threadIdx.x];
}

// ---------------------------------------------------------------------------
// agg: grid (BATCH, NSLICE), 256 threads (8 warps x 8 rows each).
// agg[b,n] = mask[n] * (k[n].qsum - k[n].q[n])
// ---------------------------------------------------------------------------
__global__ __launch_bounds__(256)
void agg_kernel(const float* __restrict__ mask) {
    const int b = blockIdx.x, s = blockIdx.y;
    const int tid = threadIdx.x, warp = tid >> 5, lane = tid & 31;
    const float* __restrict__ Kb = g_K + (size_t)b * NATOM * DIMP;
    const float* __restrict__ Qb = g_Q + (size_t)b * NATOM * DIMP;
    const float* __restrict__ m  = mask + (size_t)b * NATOM;

    __shared__ float qs[DIMP];
    if (tid < DIMP) {
        float a = 0.0f;
        #pragma unroll
        for (int p = 0; p < NSLICE; p++) a += g_qsum_part[b][p][tid];
        qs[tid] = a;
    }
    __syncthreads();

    const float4 qsv = *(const float4*)&qs[lane * 4];
    #pragma unroll
    for (int r = 0; r < 8; r++) {
        const int n = s * SLATOM + warp * 8 + r;
        const float4 k4 = *(const float4*)(Kb + (size_t)n * DIMP + lane * 4);
        const float4 q4 = *(const float4*)(Qb + (size_t)n * DIMP + lane * 4);
        float s1 = k4.x * qsv.x + k4.y * qsv.y + k4.z * qsv.z + k4.w * qsv.w;
        float s2 = k4.x * q4.x  + k4.y * q4.y  + k4.z * q4.z  + k4.w * q4.w;
        #pragma unroll
        for (int o = 16; o; o >>= 1) {
            s1 += __shfl_down_sync(0xffffffffu, s1, o);
            s2 += __shfl_down_sync(0xffffffffu, s2, o);
        }
        if (lane == 0) g_agg[(size_t)b * NATOM + n] = m[n] * (s1 - s2);
    }
}

// ---------------------------------------------------------------------------
// softmax: grid BATCH, 512 threads. normalize -> masked softmax -> attn out.
// ---------------------------------------------------------------------------
__device__ __forceinline__ float block_reduce_sum(float v, float* red) {
    int lane = threadIdx.x & 31, warp = threadIdx.x >> 5;
    #pragma unroll
    for (int o = 16; o; o >>= 1) v += __shfl_down_sync(0xffffffffu, v, o);
    if (lane == 0) red[warp] = v;
    __syncthreads();
    if (warp == 0) {
        v = (lane < 16) ? red[lane] : 0.0f;
        #pragma unroll
        for (int o = 8; o; o >>= 1) v += __shfl_down_sync(0xffffffffu, v, o);
        if (lane == 0) red[16] = v;
    }
    __syncthreads();
    float r = red[16];
    __syncthreads();
    return r;
}

__device__ __forceinline__ float block_reduce_max(float v, float* red) {
    int lane = threadIdx.x & 31, warp = threadIdx.x >> 5;
    #pragma unroll
    for (int o = 16; o; o >>= 1) v = fmaxf(v, __shfl_down_sync(0xffffffffu, v, o));
    if (lane == 0) red[warp] = v;
    __syncthreads();
    if (warp == 0) {
        v = (lane < 16) ? red[lane] : -INFINITY;
        #pragma unroll
        for (int o = 8; o; o >>= 1) v = fmaxf(v, __shfl_down_sync(0xffffffffu, v, o));
        if (lane == 0) red[16] = v;
    }
    __syncthreads();
    float r = red[16];
    __syncthreads();
    return r;
}

__global__ __launch_bounds__(512)
void softmax_kernel(const float* __restrict__ mask, float* __restrict__ out) {
    const int b = blockIdx.x, tid = threadIdx.x;
    __shared__ float red[17];

    const float v  = g_agg[(size_t)b * NATOM + tid];
    const float mv = mask[(size_t)b * NATOM + tid];

    const float total = block_reduce_sum(v * v, red);
    const float nrm = sqrtf(total);
    const float x = v / nrm + (1.0f - mv) * (-1e9f);
    const float mx = block_reduce_max(x, red);
    const float e = expf(x - mx);
    const float denom = block_reduce_sum(e, red);
    const float attn = e / denom;
    out[(size_t)b * NATOM + tid] = attn;
    g_attnW[(size_t)b * NATOM + tid] = attn * mv;
}

// ---------------------------------------------------------------------------
// ctx_part: grid (BATCH, NSLICE), 256 threads. Partial context sums.
// ---------------------------------------------------------------------------
__global__ __launch_bounds__(256)
void ctx_part_kernel() {
    const int b = blockIdx.x, s = blockIdx.y;
    const int d = threadIdx.x & 127, h = threadIdx.x >> 7;
    const float* __restrict__ Kb = g_K + ((size_t)b * NATOM + s * SLATOM) * DIMP;

    __shared__ float aw[SLATOM];
    __shared__ float part[2][DIMP];
    if (threadIdx.x < SLATOM)
        aw[threadIdx.x] = g_attnW[(size_t)b * NATOM + s * SLATOM + threadIdx.x];
    __syncthreads();

    float acc = 0.0f;
    const int n0 = h * (SLATOM / 2);
    #pragma unroll 4
    for (int n = n0; n < n0 + SLATOM / 2; n++)
        acc += aw[n] * Kb[(size_t)n * DIMP + d];
    part[h][d] = acc;
    __syncthreads();
    if (threadIdx.x < DIMP)
        g_ctx_part[b][s][threadIdx.x] = part[0][threadIdx.x] + part[1][threadIdx.x];
}

// ---------------------------------------------------------------------------
// ctx_reduce: grid BATCH, 128 threads. Fixed-order sum of slice partials.
// ---------------------------------------------------------------------------
__global__ __launch_bounds__(128)
void ctx_reduce_kernel(float* __restrict__ out) {
    const int b = blockIdx.x, d = threadIdx.x;
    float a = 0.0f;
    #pragma unroll
    for (int s = 0; s < NSLICE; s++) a += g_ctx_part[b][s][d];
    out[(size_t)BATCH * NATOM + (size_t)b * DIMP + d] = a;
}

// ---------------------------------------------------------------------------
extern "C" void kernel_launch(void* const* d_in, const int* in_sizes, int n_in,
                              void* d_out, int out_size) {
    const float* atom_query = (const float*)d_in[0];
    const float* mask       = (const float*)d_in[1];
    const float* Wq         = (const float*)d_in[2];
    const float* bq         = (const float*)d_in[3];
    const float* Wk         = (const float*)d_in[4];
    const float* bk         = (const float*)d_in[5];
    float* out = (float*)d_out;

    convertA_kernel<<<MROWS * 32 / 512, 512>>>(atom_query);
    convertB_kernel<<<32, 256>>>(Wq, Wk, bq, bk);
    wmma_gemm_kernel<<<dim3(MROWS / 128, 2), 256>>>();
    qsum_part_kernel<<<dim3(BATCH, NSLICE), 256>>>(mask);
    agg_kernel<<<dim3(BATCH, NSLICE), 256>>>(mask);
    softmax_kernel<<<BATCH, 512>>>(mask, out);
    ctx_part_kernel<<<dim3(BATCH, NSLICE), 256>>>();
    ctx_reduce_kernel<<<BATCH, 128>>>(out);
}

// round 6
// speedup vs baseline: 2.2253x; 1.2230x over previous
#include <cuda_runtime.h>
#include <cuda_bf16.h>
#include <mma.h>
#include <math.h>
#include <stdint.h>

using namespace nvcuda;

// Problem constants
#define BATCH 64
#define NATOM 512
#define DFEAT 128
#define DIMP  128
#define MROWS (BATCH * NATOM)      // 32768
#define NCOLS (2 * DIMP)           // 256 (q | k fused in n)
#define NSLICE 8
#define SLATOM (NATOM / NSLICE)    // 64
#define NTILES (MROWS / 128)       // 256 m-tiles

// smem strides (elements)
#define ASTRIDE 40                 // 32 + 8 pad (bf16)
#define BSTRIDE 264                // 256 + 8 pad (bf16)
#define QSTRIDE 132                // 128 + 4 pad (fp32)

// dynamic smem layout (bytes)
#define OFF_AH   0
#define OFF_AL   (128 * ASTRIDE * 2)                    // 10240
#define OFF_BH   (OFF_AL + 128 * ASTRIDE * 2)           // 20480
#define OFF_BL   (OFF_BH + 32 * BSTRIDE * 2)            // 37376
#define STAGE_BYTES (OFF_BL + 32 * BSTRIDE * 2)         // 54272
#define EPI_BYTES (2 * 128 * QSTRIDE * 4)               // 135168 (Qs | Ks)
#define DSMEM_BYTES (EPI_BYTES > STAGE_BYTES ? EPI_BYTES : STAGE_BYTES)

// Device scratch
__device__ __nv_bfloat16 g_Bhl[2][DFEAT][NCOLS];       // Bh, Bl  (128 KB)
__device__ float g_bias[NCOLS];
__device__ float g_K[(size_t)MROWS * DIMP];            // 16 MB
__device__ float g_qsum_part[NTILES][DIMP];            // 128 KB
__device__ float g_diag[MROWS];                        // 128 KB
__device__ float g_agg[MROWS];                         // 128 KB
__device__ float g_attnW[MROWS];                       // 128 KB
__device__ float g_ctx_part[BATCH][NSLICE][DIMP];      // 256 KB

// ---------------------------------------------------------------------------
// convertB: Wq|Wk fp32 -> g_Bhl (hi, lo bf16), g_bias
// ---------------------------------------------------------------------------
__global__ __launch_bounds__(256)
void convertB_kernel(const float* __restrict__ Wq, const float* __restrict__ Wk,
                     const float* __restrict__ bq, const float* __restrict__ bk) {
    int idx = blockIdx.x * blockDim.x + threadIdx.x;   // < 8192
    int k  = idx >> 6;
    int n4 = (idx & 63) << 2;

    float4 w = (n4 < DIMP)
        ? *(const float4*)(Wq + (size_t)k * DIMP + n4)
        : *(const float4*)(Wk + (size_t)k * DIMP + (n4 - DIMP));

    float v[4] = {w.x, w.y, w.z, w.w};
    uint16_t h[4], l[4];
    #pragma unroll
    for (int i = 0; i < 4; i++) {
        __nv_bfloat16 hb = __float2bfloat16(v[i]);
        __nv_bfloat16 lb = __float2bfloat16(v[i] - __bfloat162float(hb));
        h[i] = __bfloat16_as_ushort(hb);
        l[i] = __bfloat16_as_ushort(lb);
    }
    *(uint2*)(&g_Bhl[0][k][n4]) = make_uint2(((uint32_t)h[1] << 16) | h[0],
                                             ((uint32_t)h[3] << 16) | h[2]);
    *(uint2*)(&g_Bhl[1][k][n4]) = make_uint2(((uint32_t)l[1] << 16) | l[0],
                                             ((uint32_t)l[3] << 16) | l[2]);

    if (idx < DIMP) { g_bias[idx] = bq[idx]; g_bias[DIMP + idx] = bk[idx]; }
}

// ---------------------------------------------------------------------------
// Fused GEMM: 256 CTAs x 512 threads. Tile 128m x 256n, K=3x128 bf16 split.
// Loads fp32 A, converts in-register. Epilogue: writes K, qsum partials, diag.
// ---------------------------------------------------------------------------
__global__ __launch_bounds__(512, 1)
void gemm_fused_kernel(const float* __restrict__ A, const float* __restrict__ mask) {
    extern __shared__ char dsm[];
    __shared__ float maskS[128];
    __shared__ float partQ[4][DIMP];

    const int tid  = threadIdx.x;
    const int warp = tid >> 5;
    const int lane = tid & 31;
    const int mt   = blockIdx.x;
    const int bm   = mt * 128;
    const int wm   = (warp >> 2) * 32;     // 4 warp-rows of 32
    const int wn   = (warp & 3) * 64;      // 4 warp-cols of 64

    // --- accumulator init with bias (replicated 16-row tile in dsm) ---
    float* biasT = (float*)dsm;            // 16 x 256
    for (int i = tid; i < 16 * NCOLS; i += 512) biasT[i] = g_bias[i & 255];
    __syncthreads();

    wmma::fragment<wmma::accumulator, 16, 16, 16, float> acc[2][4];
    #pragma unroll
    for (int i = 0; i < 2; i++)
        #pragma unroll
        for (int j = 0; j < 4; j++)
            wmma::load_matrix_sync(acc[i][j], biasT + wn + j * 16, NCOLS, wmma::mem_row_major);
    __syncthreads();

    __nv_bfloat16* Ah_s = (__nv_bfloat16*)(dsm + OFF_AH);
    __nv_bfloat16* Al_s = (__nv_bfloat16*)(dsm + OFF_AL);
    __nv_bfloat16* Bh_s = (__nv_bfloat16*)(dsm + OFF_BH);
    __nv_bfloat16* Bl_s = (__nv_bfloat16*)(dsm + OFF_BL);

    // --- mainloop: 4 chunks of k=32, 3 passes each ---
    for (int kc = 0; kc < 4; kc++) {
        // A fp32 -> hi/lo bf16 (1024 float4, 2 per thread)
        #pragma unroll
        for (int v = 0; v < 2; v++) {
            int f = tid + v * 512;
            int r = f >> 3, c4 = (f & 7) * 4;
            float4 a = *(const float4*)(A + (size_t)(bm + r) * DFEAT + kc * 32 + c4);
            float vv[4] = {a.x, a.y, a.z, a.w};
            uint16_t h[4], l[4];
            #pragma unroll
            for (int i = 0; i < 4; i++) {
                __nv_bfloat16 hb = __float2bfloat16(vv[i]);
                __nv_bfloat16 lb = __float2bfloat16(vv[i] - __bfloat162float(hb));
                h[i] = __bfloat16_as_ushort(hb);
                l[i] = __bfloat16_as_ushort(lb);
            }
            *(uint2*)(&Ah_s[r * ASTRIDE + c4]) = make_uint2(((uint32_t)h[1] << 16) | h[0],
                                                            ((uint32_t)h[3] << 16) | h[2]);
            *(uint2*)(&Al_s[r * ASTRIDE + c4]) = make_uint2(((uint32_t)l[1] << 16) | l[0],
                                                            ((uint32_t)l[3] << 16) | l[2]);
        }
        // B chunks (1024 uint4 each, 2 per thread)
        #pragma unroll
        for (int v = 0; v < 2; v++) {
            int f = tid + v * 512;
            int br = f >> 5, bc = (f & 31) * 8;
            *(uint4*)(&Bh_s[br * BSTRIDE + bc]) = *(const uint4*)(&g_Bhl[0][kc * 32 + br][bc]);
            *(uint4*)(&Bl_s[br * BSTRIDE + bc]) = *(const uint4*)(&g_Bhl[1][kc * 32 + br][bc]);
        }
        __syncthreads();

        #pragma unroll
        for (int pass = 0; pass < 3; pass++) {
            const __nv_bfloat16* Ap = (pass == 1) ? Al_s : Ah_s;
            const __nv_bfloat16* Bp = (pass == 2) ? Bl_s : Bh_s;
            #pragma unroll
            for (int kk = 0; kk < 32; kk += 16) {
                wmma::fragment<wmma::matrix_a, 16, 16, 16, __nv_bfloat16, wmma::row_major> af[2];
                wmma::fragment<wmma::matrix_b, 16, 16, 16, __nv_bfloat16, wmma::row_major> bf[4];
                #pragma unroll
                for (int i = 0; i < 2; i++)
                    wmma::load_matrix_sync(af[i], Ap + (wm + i * 16) * ASTRIDE + kk, ASTRIDE);
                #pragma unroll
                for (int j = 0; j < 4; j++)
                    wmma::load_matrix_sync(bf[j], Bp + kk * BSTRIDE + wn + j * 16, BSTRIDE);
                #pragma unroll
                for (int i = 0; i < 2; i++)
                    #pragma unroll
                    for (int j = 0; j < 4; j++)
                        wmma::mma_sync(acc[i][j], af[i], bf[j], acc[i][j]);
            }
        }
        __syncthreads();
    }

    // --- epilogue: overlay Qs|Ks in dsm ---
    float* Qs = (float*)dsm;                       // 128 x QSTRIDE
    float* Ks = Qs + 128 * QSTRIDE;
    #pragma unroll
    for (int i = 0; i < 2; i++) {
        #pragma unroll
        for (int j = 0; j < 4; j++) {
            int n = wn + j * 16;
            float* t = (n < DIMP) ? (Qs + (wm + i * 16) * QSTRIDE + n)
                                  : (Ks + (wm + i * 16) * QSTRIDE + (n - DIMP));
            wmma::store_matrix_sync(t, acc[i][j], QSTRIDE, wmma::mem_row_major);
        }
    }
    if (tid < 128) maskS[tid] = mask[(size_t)bm + tid];
    __syncthreads();

    // write K tile to global (4096 float4, 8 per thread)
    #pragma unroll
    for (int v = 0; v < 8; v++) {
        int f = tid + v * 512;
        int r = f >> 5, c4 = (f & 31) * 4;
        *(float4*)(g_K + (size_t)(bm + r) * DIMP + c4) = *(float4*)(&Ks[r * QSTRIDE + c4]);
    }

    // qsum partial: 4 row-groups of 32
    {
        const int d = tid & 127, h = tid >> 7;
        float acc_q = 0.0f;
        #pragma unroll 8
        for (int n = h * 32; n < h * 32 + 32; n++)
            acc_q += maskS[n] * Qs[n * QSTRIDE + d];
        partQ[h][d] = acc_q;
    }
    __syncthreads();
    if (tid < DIMP)
        g_qsum_part[mt][tid] = partQ[0][tid] + partQ[1][tid] + partQ[2][tid] + partQ[3][tid];

    // diag[n] = q[n] . k[n]  (16 warps x 8 rows)
    #pragma unroll
    for (int rr = 0; rr < 8; rr++) {
        const int n = warp * 8 + rr;
        const float4 q4 = *(const float4*)(&Qs[n * QSTRIDE + lane * 4]);
        const float4 k4 = *(const float4*)(&Ks[n * QSTRIDE + lane * 4]);
        float s = q4.x * k4.x + q4.y * k4.y + q4.z * k4.z + q4.w * k4.w;
        #pragma unroll
        for (int o = 16; o; o >>= 1) s += __shfl_down_sync(0xffffffffu, s, o);
        if (lane == 0) g_diag[(size_t)bm + n] = s;
    }
}

// ---------------------------------------------------------------------------
// agg: grid (BATCH, NSLICE), 256 threads. agg[n] = m[n]*(k[n].qsum - diag[n])
// ---------------------------------------------------------------------------
__global__ __launch_bounds__(256)
void agg_kernel(const float* __restrict__ mask) {
    const int b = blockIdx.x, s = blockIdx.y;
    const int tid = threadIdx.x, warp = tid >> 5, lane = tid & 31;
    const float* __restrict__ Kb = g_K + (size_t)b * NATOM * DIMP;
    const float* __restrict__ m  = mask + (size_t)b * NATOM;

    __shared__ float qs[DIMP];
    if (tid < DIMP) {
        float a = g_qsum_part[b * 4 + 0][tid] + g_qsum_part[b * 4 + 1][tid]
                + g_qsum_part[b * 4 + 2][tid] + g_qsum_part[b * 4 + 3][tid];
        qs[tid] = a;
    }
    __syncthreads();

    const float4 qsv = *(const float4*)&qs[lane * 4];
    #pragma unroll
    for (int r = 0; r < 8; r++) {
        const int n = s * SLATOM + warp * 8 + r;
        const float4 k4 = *(const float4*)(Kb + (size_t)n * DIMP + lane * 4);
        float s1 = k4.x * qsv.x + k4.y * qsv.y + k4.z * qsv.z + k4.w * qsv.w;
        #pragma unroll
        for (int o = 16; o; o >>= 1) s1 += __shfl_down_sync(0xffffffffu, s1, o);
        if (lane == 0)
            g_agg[(size_t)b * NATOM + n] = m[n] * (s1 - g_diag[(size_t)b * NATOM + n]);
    }
}

// ---------------------------------------------------------------------------
// softmax helpers + kernel
// ---------------------------------------------------------------------------
__device__ __forceinline__ float block_reduce_sum(float v, float* red) {
    int lane = threadIdx.x & 31, warp = threadIdx.x >> 5;
    #pragma unroll
    for (int o = 16; o; o >>= 1) v += __shfl_down_sync(0xffffffffu, v, o);
    if (lane == 0) red[warp] = v;
    __syncthreads();
    if (warp == 0) {
        v = (lane < 16) ? red[lane] : 0.0f;
        #pragma unroll
        for (int o = 8; o; o >>= 1) v += __shfl_down_sync(0xffffffffu, v, o);
        if (lane == 0) red[16] = v;
    }
    __syncthreads();
    float r = red[16];
    __syncthreads();
    return r;
}

__device__ __forceinline__ float block_reduce_max(float v, float* red) {
    int lane = threadIdx.x & 31, warp = threadIdx.x >> 5;
    #pragma unroll
    for (int o = 16; o; o >>= 1) v = fmaxf(v, __shfl_down_sync(0xffffffffu, v, o));
    if (lane == 0) red[warp] = v;
    __syncthreads();
    if (warp == 0) {
        v = (lane < 16) ? red[lane] : -INFINITY;
        #pragma unroll
        for (int o = 8; o; o >>= 1) v = fmaxf(v, __shfl_down_sync(0xffffffffu, v, o));
        if (lane == 0) red[16] = v;
    }
    __syncthreads();
    float r = red[16];
    __syncthreads();
    return r;
}

__global__ __launch_bounds__(512)
void softmax_kernel(const float* __restrict__ mask, float* __restrict__ out) {
    const int b = blockIdx.x, tid = threadIdx.x;
    __shared__ float red[17];

    const float v  = g_agg[(size_t)b * NATOM + tid];
    const float mv = mask[(size_t)b * NATOM + tid];

    const float total = block_reduce_sum(v * v, red);
    const float nrm = sqrtf(total);
    const float x = v / nrm + (1.0f - mv) * (-1e9f);
    const float mx = block_reduce_max(x, red);
    const float e = expf(x - mx);
    const float denom = block_reduce_sum(e, red);
    const float attn = e / denom;
    out[(size_t)b * NATOM + tid] = attn;
    g_attnW[(size_t)b * NATOM + tid] = attn * mv;
}

// ---------------------------------------------------------------------------
// ctx_part + ctx_reduce
// ---------------------------------------------------------------------------
__global__ __launch_bounds__(256)
void ctx_part_kernel() {
    const int b = blockIdx.x, s = blockIdx.y;
    const int d = threadIdx.x & 127, h = threadIdx.x >> 7;
    const float* __restrict__ Kb = g_K + ((size_t)b * NATOM + s * SLATOM) * DIMP;

    __shared__ float aw[SLATOM];
    __shared__ float part[2][DIMP];
    if (threadIdx.x < SLATOM)
        aw[threadIdx.x] = g_attnW[(size_t)b * NATOM + s * SLATOM + threadIdx.x];
    __syncthreads();

    float acc = 0.0f;
    #pragma unroll 4
    for (int n = h * (SLATOM / 2); n < (h + 1) * (SLATOM / 2); n++)
        acc += aw[n] * Kb[(size_t)n * DIMP + d];
    part[h][d] = acc;
    __syncthreads();
    if (threadIdx.x < DIMP)
        g_ctx_part[b][s][threadIdx.x] = part[0][threadIdx.x] + part[1][threadIdx.x];
}

__global__ __launch_bounds__(128)
void ctx_reduce_kernel(float* __restrict__ out) {
    const int b = blockIdx.x, d = threadIdx.x;
    float a = 0.0f;
    #pragma unroll
    for (int s = 0; s < NSLICE; s++) a += g_ctx_part[b][s][d];
    out[(size_t)BATCH * NATOM + (size_t)b * DIMP + d] = a;
}

// ---------------------------------------------------------------------------
extern "C" void kernel_launch(void* const* d_in, const int* in_sizes, int n_in,
                              void* d_out, int out_size) {
    const float* atom_query = (const float*)d_in[0];
    const float* mask       = (const float*)d_in[1];
    const float* Wq         = (const float*)d_in[2];
    const float* bq         = (const float*)d_in[3];
    const float* Wk         = (const float*)d_in[4];
    const float* bk         = (const float*)d_in[5];
    float* out = (float*)d_out;

    static int smem_set = 0;
    if (!smem_set) {
        cudaFuncSetAttribute(gemm_fused_kernel,
                             cudaFuncAttributeMaxDynamicSharedMemorySize, DSMEM_BYTES);
        smem_set = 1;
    }

    convertB_kernel<<<32, 256>>>(Wq, Wk, bq, bk);
    gemm_fused_kernel<<<NTILES, 512, DSMEM_BYTES>>>(atom_query, mask);
    agg_kernel<<<dim3(BATCH, NSLICE), 256>>>(mask);
    softmax_kernel<<<BATCH, 512>>>(mask, out);
    ctx_part_kernel<<<dim3(BATCH, NSLICE), 256>>>();
    ctx_reduce_kernel<<<BATCH, 128>>>(out);
}

// round 7
// speedup vs baseline: 2.2942x; 1.0310x over previous
#include <cuda_runtime.h>
#include <cuda_bf16.h>
#include <mma.h>
#include <math.h>
#include <stdint.h>

using namespace nvcuda;

// Problem constants
#define BATCH 64
#define NATOM 512
#define DFEAT 128
#define DIMP  128
#define MROWS (BATCH * NATOM)      // 32768
#define NCOLS (2 * DIMP)           // 256 (q | k fused in n)
#define NTILES (MROWS / 128)       // 256 m-tiles (4 per batch)

// smem strides (elements)
#define ASTRIDE 40                 // 32 + 8 pad (bf16)
#define BSTRIDE 264                // 256 + 8 pad (bf16)
#define QSTRIDE 132                // 128 + 4 pad (fp32)

// dynamic smem layout (bytes)
#define OFF_AH   0
#define OFF_AL   (128 * ASTRIDE * 2)                    // 10240
#define OFF_BH   (OFF_AL + 128 * ASTRIDE * 2)           // 20480
#define OFF_BL   (OFF_BH + 32 * BSTRIDE * 2)            // 37376
#define STAGE_BYTES (OFF_BL + 32 * BSTRIDE * 2)         // 54272
#define EPI_BYTES (2 * 128 * QSTRIDE * 4)               // 135168 (Qs | Ks)
#define DSMEM_BYTES (EPI_BYTES > STAGE_BYTES ? EPI_BYTES : STAGE_BYTES)

// Device scratch
__device__ __nv_bfloat16 g_Bhl[2][DFEAT][NCOLS];       // Bh, Bl (128 KB)
__device__ float g_bias[NCOLS];
__device__ float g_Kt[BATCH][DIMP][NATOM];             // K transposed, 16 MB
__device__ float g_qsum_part[NTILES][DIMP];            // 128 KB
__device__ float g_diag[MROWS];                        // 128 KB

// ---------------------------------------------------------------------------
// convertB: Wq|Wk fp32 -> g_Bhl (hi, lo bf16), g_bias
// ---------------------------------------------------------------------------
__global__ __launch_bounds__(256)
void convertB_kernel(const float* __restrict__ Wq, const float* __restrict__ Wk,
                     const float* __restrict__ bq, const float* __restrict__ bk) {
    int idx = blockIdx.x * blockDim.x + threadIdx.x;   // < 8192
    int k  = idx >> 6;
    int n4 = (idx & 63) << 2;

    float4 w = (n4 < DIMP)
        ? *(const float4*)(Wq + (size_t)k * DIMP + n4)
        : *(const float4*)(Wk + (size_t)k * DIMP + (n4 - DIMP));

    float v[4] = {w.x, w.y, w.z, w.w};
    uint16_t h[4], l[4];
    #pragma unroll
    for (int i = 0; i < 4; i++) {
        __nv_bfloat16 hb = __float2bfloat16(v[i]);
        __nv_bfloat16 lb = __float2bfloat16(v[i] - __bfloat162float(hb));
        h[i] = __bfloat16_as_ushort(hb);
        l[i] = __bfloat16_as_ushort(lb);
    }
    *(uint2*)(&g_Bhl[0][k][n4]) = make_uint2(((uint32_t)h[1] << 16) | h[0],
                                             ((uint32_t)h[3] << 16) | h[2]);
    *(uint2*)(&g_Bhl[1][k][n4]) = make_uint2(((uint32_t)l[1] << 16) | l[0],
                                             ((uint32_t)l[3] << 16) | l[2]);

    if (idx < DIMP) { g_bias[idx] = bq[idx]; g_bias[DIMP + idx] = bk[idx]; }
}

// ---------------------------------------------------------------------------
// Fused GEMM: 256 CTAs x 512 threads. Tile 128m x 256n, K=3x128 bf16 split.
// Epilogue: writes K^T (per batch), qsum partials, diag. Q never hits global.
// ---------------------------------------------------------------------------
__global__ __launch_bounds__(512, 1)
void gemm_fused_kernel(const float* __restrict__ A, const float* __restrict__ mask) {
    extern __shared__ char dsm[];
    __shared__ float maskS[128];
    __shared__ float partQ[4][DIMP];

    const int tid  = threadIdx.x;
    const int warp = tid >> 5;
    const int lane = tid & 31;
    const int mt   = blockIdx.x;
    const int bm   = mt * 128;
    const int wm   = (warp >> 2) * 32;     // 4 warp-rows of 32
    const int wn   = (warp & 3) * 64;      // 4 warp-cols of 64

    // --- accumulator init with bias (replicated 16-row tile in dsm) ---
    float* biasT = (float*)dsm;            // 16 x 256
    for (int i = tid; i < 16 * NCOLS; i += 512) biasT[i] = g_bias[i & 255];
    __syncthreads();

    wmma::fragment<wmma::accumulator, 16, 16, 16, float> acc[2][4];
    #pragma unroll
    for (int i = 0; i < 2; i++)
        #pragma unroll
        for (int j = 0; j < 4; j++)
            wmma::load_matrix_sync(acc[i][j], biasT + wn + j * 16, NCOLS, wmma::mem_row_major);
    __syncthreads();

    __nv_bfloat16* Ah_s = (__nv_bfloat16*)(dsm + OFF_AH);
    __nv_bfloat16* Al_s = (__nv_bfloat16*)(dsm + OFF_AL);
    __nv_bfloat16* Bh_s = (__nv_bfloat16*)(dsm + OFF_BH);
    __nv_bfloat16* Bl_s = (__nv_bfloat16*)(dsm + OFF_BL);

    // --- mainloop: 4 chunks of k=32, 3 passes each ---
    for (int kc = 0; kc < 4; kc++) {
        #pragma unroll
        for (int v = 0; v < 2; v++) {
            int f = tid + v * 512;
            int r = f >> 3, c4 = (f & 7) * 4;
            float4 a = *(const float4*)(A + (size_t)(bm + r) * DFEAT + kc * 32 + c4);
            float vv[4] = {a.x, a.y, a.z, a.w};
            uint16_t h[4], l[4];
            #pragma unroll
            for (int i = 0; i < 4; i++) {
                __nv_bfloat16 hb = __float2bfloat16(vv[i]);
                __nv_bfloat16 lb = __float2bfloat16(vv[i] - __bfloat162float(hb));
                h[i] = __bfloat16_as_ushort(hb);
                l[i] = __bfloat16_as_ushort(lb);
            }
            *(uint2*)(&Ah_s[r * ASTRIDE + c4]) = make_uint2(((uint32_t)h[1] << 16) | h[0],
                                                            ((uint32_t)h[3] << 16) | h[2]);
            *(uint2*)(&Al_s[r * ASTRIDE + c4]) = make_uint2(((uint32_t)l[1] << 16) | l[0],
                                                            ((uint32_t)l[3] << 16) | l[2]);
        }
        #pragma unroll
        for (int v = 0; v < 2; v++) {
            int f = tid + v * 512;
            int br = f >> 5, bc = (f & 31) * 8;
            *(uint4*)(&Bh_s[br * BSTRIDE + bc]) = *(const uint4*)(&g_Bhl[0][kc * 32 + br][bc]);
            *(uint4*)(&Bl_s[br * BSTRIDE + bc]) = *(const uint4*)(&g_Bhl[1][kc * 32 + br][bc]);
        }
        __syncthreads();

        #pragma unroll
        for (int pass = 0; pass < 3; pass++) {
            const __nv_bfloat16* Ap = (pass == 1) ? Al_s : Ah_s;
            const __nv_bfloat16* Bp = (pass == 2) ? Bl_s : Bh_s;
            #pragma unroll
            for (int kk = 0; kk < 32; kk += 16) {
                wmma::fragment<wmma::matrix_a, 16, 16, 16, __nv_bfloat16, wmma::row_major> af[2];
                wmma::fragment<wmma::matrix_b, 16, 16, 16, __nv_bfloat16, wmma::row_major> bf[4];
                #pragma unroll
                for (int i = 0; i < 2; i++)
                    wmma::load_matrix_sync(af[i], Ap + (wm + i * 16) * ASTRIDE + kk, ASTRIDE);
                #pragma unroll
                for (int j = 0; j < 4; j++)
                    wmma::load_matrix_sync(bf[j], Bp + kk * BSTRIDE + wn + j * 16, BSTRIDE);
                #pragma unroll
                for (int i = 0; i < 2; i++)
                    #pragma unroll
                    for (int j = 0; j < 4; j++)
                        wmma::mma_sync(acc[i][j], af[i], bf[j], acc[i][j]);
            }
        }
        __syncthreads();
    }

    // --- epilogue: overlay Qs|Ks in dsm ---
    float* Qs = (float*)dsm;                       // 128 x QSTRIDE
    float* Ks = Qs + 128 * QSTRIDE;
    #pragma unroll
    for (int i = 0; i < 2; i++) {
        #pragma unroll
        for (int j = 0; j < 4; j++) {
            int n = wn + j * 16;
            float* t = (n < DIMP) ? (Qs + (wm + i * 16) * QSTRIDE + n)
                                  : (Ks + (wm + i * 16) * QSTRIDE + (n - DIMP));
            wmma::store_matrix_sync(t, acc[i][j], QSTRIDE, wmma::mem_row_major);
        }
    }
    if (tid < 128) maskS[tid] = mask[(size_t)bm + tid];
    __syncthreads();

    // K^T write: batch b, atom slot ns..ns+127. Coalesced stores per d-row.
    {
        const int b = mt >> 2, ns = (mt & 3) * 128;
        #pragma unroll
        for (int v = 0; v < 8; v++) {
            int f = v * 512 + tid;        // 0..4095
            int n = f & 127;
            int d4 = (f >> 7) * 4;        // 0..124
            float4 kv = *(float4*)(&Ks[n * QSTRIDE + d4]);
            g_Kt[b][d4 + 0][ns + n] = kv.x;
            g_Kt[b][d4 + 1][ns + n] = kv.y;
            g_Kt[b][d4 + 2][ns + n] = kv.z;
            g_Kt[b][d4 + 3][ns + n] = kv.w;
        }
    }

    // qsum partial: 4 row-groups of 32
    {
        const int d = tid & 127, h = tid >> 7;
        float acc_q = 0.0f;
        #pragma unroll 8
        for (int n = h * 32; n < h * 32 + 32; n++)
            acc_q += maskS[n] * Qs[n * QSTRIDE + d];
        partQ[h][d] = acc_q;
    }
    __syncthreads();
    if (tid < DIMP)
        g_qsum_part[mt][tid] = partQ[0][tid] + partQ[1][tid] + partQ[2][tid] + partQ[3][tid];

    // diag[n] = q[n] . k[n]  (16 warps x 8 rows)
    #pragma unroll
    for (int rr = 0; rr < 8; rr++) {
        const int n = warp * 8 + rr;
        const float4 q4 = *(const float4*)(&Qs[n * QSTRIDE + lane * 4]);
        const float4 k4 = *(const float4*)(&Ks[n * QSTRIDE + lane * 4]);
        float s = q4.x * k4.x + q4.y * k4.y + q4.z * k4.z + q4.w * k4.w;
        #pragma unroll
        for (int o = 16; o; o >>= 1) s += __shfl_down_sync(0xffffffffu, s, o);
        if (lane == 0) g_diag[(size_t)bm + n] = s;
    }
}

// ---------------------------------------------------------------------------
// Block reductions (512 threads, 16 warps)
// ---------------------------------------------------------------------------
__device__ __forceinline__ float block_reduce_sum(float v, float* red) {
    int lane = threadIdx.x & 31, warp = threadIdx.x >> 5;
    #pragma unroll
    for (int o = 16; o; o >>= 1) v += __shfl_down_sync(0xffffffffu, v, o);
    if (lane == 0) red[warp] = v;
    __syncthreads();
    if (warp == 0) {
        v = (lane < 16) ? red[lane] : 0.0f;
        #pragma unroll
        for (int o = 8; o; o >>= 1) v += __shfl_down_sync(0xffffffffu, v, o);
        if (lane == 0) red[16] = v;
    }
    __syncthreads();
    float r = red[16];
    __syncthreads();
    return r;
}

__device__ __forceinline__ float block_reduce_max(float v, float* red) {
    int lane = threadIdx.x & 31, warp = threadIdx.x >> 5;
    #pragma unroll
    for (int o = 16; o; o >>= 1) v = fmaxf(v, __shfl_down_sync(0xffffffffu, v, o));
    if (lane == 0) red[warp] = v;
    __syncthreads();
    if (warp == 0) {
        v = (lane < 16) ? red[lane] : -INFINITY;
        #pragma unroll
        for (int o = 8; o; o >>= 1) v = fmaxf(v, __shfl_down_sync(0xffffffffu, v, o));
        if (lane == 0) red[16] = v;
    }
    __syncthreads();
    float r = red[16];
    __syncthreads();
    return r;
}

// ---------------------------------------------------------------------------
// attn_fused: grid BATCH, 512 threads. agg -> normalize -> softmax -> context.
// All K accesses go through K^T: coalesced streaming, no per-row shuffles.
// ---------------------------------------------------------------------------
__global__ __launch_bounds__(512)
void attn_fused_kernel(const float* __restrict__ mask, float* __restrict__ out) {
    const int b = blockIdx.x, tid = threadIdx.x;
    const int lane = tid & 31, warp = tid >> 5;
    __shared__ float qs[DIMP];
    __shared__ float aw[NATOM];
    __shared__ float red[17];

    if (tid < DIMP)
        qs[tid] = g_qsum_part[b * 4 + 0][tid] + g_qsum_part[b * 4 + 1][tid]
                + g_qsum_part[b * 4 + 2][tid] + g_qsum_part[b * 4 + 3][tid];
    __syncthreads();

    const float* __restrict__ Kt = &g_Kt[b][0][0];   // [128][512]

    // agg[n] = mask[n] * (k[n].qsum - diag[n]); thread-per-atom, coalesced
    float acc = 0.0f;
    #pragma unroll 8
    for (int d = 0; d < DIMP; d++)
        acc = fmaf(Kt[d * NATOM + tid], qs[d], acc);
    const float mv = mask[(size_t)b * NATOM + tid];
    const float v = mv * (acc - g_diag[(size_t)b * NATOM + tid]);

    // normalize over atoms, masked softmax
    const float total = block_reduce_sum(v * v, red);
    const float nrm = sqrtf(total);
    const float x = v / nrm + (1.0f - mv) * (-1e9f);
    const float mx = block_reduce_max(x, red);
    const float e = expf(x - mx);
    const float denom = block_reduce_sum(e, red);
    const float attn = e / denom;
    out[(size_t)b * NATOM + tid] = attn;
    aw[tid] = attn * mv;
    __syncthreads();

    // context[d] = sum_n aw[n] * Kt[d][n]; warp-per-d-row, contiguous rows
    #pragma unroll
    for (int r = 0; r < 8; r++) {
        const int d = warp * 8 + r;
        const float* row = Kt + d * NATOM;
        float s = 0.0f;
        #pragma unroll
        for (int j = 0; j < 4; j++) {
            const float4 k4 = *(const float4*)(row + j * 128 + lane * 4);
            const float4 a4 = *(const float4*)(&aw[j * 128 + lane * 4]);
            s += k4.x * a4.x + k4.y * a4.y + k4.z * a4.z + k4.w * a4.w;
        }
        #pragma unroll
        for (int o = 16; o; o >>= 1) s += __shfl_down_sync(0xffffffffu, s, o);
        if (lane == 0) out[(size_t)BATCH * NATOM + (size_t)b * DIMP + d] = s;
    }
}

// ---------------------------------------------------------------------------
extern "C" void kernel_launch(void* const* d_in, const int* in_sizes, int n_in,
                              void* d_out, int out_size) {
    const float* atom_query = (const float*)d_in[0];
    const float* mask       = (const float*)d_in[1];
    const float* Wq         = (const float*)d_in[2];
    const float* bq         = (const float*)d_in[3];
    const float* Wk         = (const float*)d_in[4];
    const float* bk         = (const float*)d_in[5];
    float* out = (float*)d_out;

    static int smem_set = 0;
    if (!smem_set) {
        cudaFuncSetAttribute(gemm_fused_kernel,
                             cudaFuncAttributeMaxDynamicSharedMemorySize, DSMEM_BYTES);
        smem_set = 1;
    }

    convertB_kernel<<<32, 256>>>(Wq, Wk, bq, bk);
    gemm_fused_kernel<<<NTILES, 512, DSMEM_BYTES>>>(atom_query, mask);
    attn_fused_kernel<<<BATCH, 512>>>(mask, out);
}

// round 8
// speedup vs baseline: 2.3830x; 1.0387x over previous
#include <cuda_runtime.h>
#include <cuda_bf16.h>
#include <mma.h>
#include <math.h>
#include <stdint.h>

using namespace nvcuda;

// Problem constants
#define BATCH 64
#define NATOM 512
#define DFEAT 128
#define DIMP  128
#define MROWS (BATCH * NATOM)      // 32768
#define NCOLS (2 * DIMP)           // 256 (q | k fused in n)
#define NTILES (MROWS / 128)       // 256 m-tiles (4 per batch)

// smem strides (elements)
#define ASTRIDE 40                 // 32 + 8 pad (bf16)
#define BSTRIDE 264                // 256 + 8 pad (bf16)
#define QSTRIDE 132                // 128 + 4 pad (fp32)

// stage layout (bytes, per buffer)
#define OFF_AH   0
#define OFF_AL   (128 * ASTRIDE * 2)                    // 10240
#define OFF_BH   (OFF_AL + 128 * ASTRIDE * 2)           // 20480
#define OFF_BL   (OFF_BH + 32 * BSTRIDE * 2)            // 37376
#define STAGE_BYTES (OFF_BL + 32 * BSTRIDE * 2)         // 54272
#define EPI_BYTES (2 * 128 * QSTRIDE * 4)               // 135168 (Qs | Ks)
#define PIPE_BYTES (2 * STAGE_BYTES)                    // 108544
#define DSMEM_BYTES (EPI_BYTES > PIPE_BYTES ? EPI_BYTES : PIPE_BYTES)

// Device scratch
__device__ float g_Kt[BATCH][DIMP][NATOM];             // K transposed, 16 MB
__device__ float g_qsum_part[NTILES][DIMP];            // 128 KB
__device__ float g_diag[MROWS];                        // 128 KB

// ---------------------------------------------------------------------------
// Fused GEMM: 256 CTAs x 512 threads. Tile 128m x 256n, K=3x128 bf16 split.
// Double-buffered k-chunks; W converted in-loader (no convertB kernel).
// Epilogue: writes K^T, qsum partials, diag. Q never hits global memory.
// ---------------------------------------------------------------------------
__global__ __launch_bounds__(512, 1)
void gemm_fused_kernel(const float* __restrict__ A,
                       const float* __restrict__ Wq, const float* __restrict__ Wk,
                       const float* __restrict__ bq, const float* __restrict__ bk,
                       const float* __restrict__ mask) {
    extern __shared__ char dsm[];
    __shared__ float maskS[128];
    __shared__ float partQ[4][DIMP];

    const int tid  = threadIdx.x;
    const int warp = tid >> 5;
    const int lane = tid & 31;
    const int mt   = blockIdx.x;
    const int bm   = mt * 128;
    const int wm   = (warp >> 2) * 32;     // 4 warp-rows of 32
    const int wn   = (warp & 3) * 64;      // 4 warp-cols of 64

    // --- accumulator init with bias (replicated 16-row tile in dsm) ---
    float* biasT = (float*)dsm;            // 16 x 256
    for (int i = tid; i < 16 * NCOLS; i += 512) {
        int col = i & 255;
        biasT[i] = (col < DIMP) ? bq[col] : bk[col - DIMP];
    }
    __syncthreads();

    wmma::fragment<wmma::accumulator, 16, 16, 16, float> acc[2][4];
    #pragma unroll
    for (int i = 0; i < 2; i++)
        #pragma unroll
        for (int j = 0; j < 4; j++)
            wmma::load_matrix_sync(acc[i][j], biasT + wn + j * 16, NCOLS, wmma::mem_row_major);
    __syncthreads();

    // loader index precompute
    const int ar0 = tid >> 3,          ac0 = (tid & 7) * 4;          // A f = tid
    const int ar1 = (tid + 512) >> 3,  ac1 = ((tid + 512) & 7) * 4;  // A f = tid+512
    int brr[4], bcc[4];
    #pragma unroll
    for (int v = 0; v < 4; v++) {
        int f = tid + v * 512;                    // 0..2047
        brr[v] = f >> 6;                          // W row in chunk (0..31)
        bcc[v] = (f & 63) * 4;                    // n col (0..252)
    }

    float4 pa[2], pb[4];
    #define FETCH(kc)                                                                   \
        do {                                                                            \
            pa[0] = *(const float4*)(A + (size_t)(bm + ar0) * DFEAT + (kc) * 32 + ac0); \
            pa[1] = *(const float4*)(A + (size_t)(bm + ar1) * DFEAT + (kc) * 32 + ac1); \
            _Pragma("unroll")                                                           \
            for (int v = 0; v < 4; v++) {                                               \
                int k = (kc) * 32 + brr[v];                                             \
                pb[v] = (bcc[v] < DIMP)                                                 \
                    ? *(const float4*)(Wq + (size_t)k * DIMP + bcc[v])                  \
                    : *(const float4*)(Wk + (size_t)k * DIMP + (bcc[v] - DIMP));        \
            }                                                                           \
        } while (0)

    #define CVT_STORE(buf)                                                              \
        do {                                                                            \
            __nv_bfloat16* AhS = (__nv_bfloat16*)(dsm + (buf) * STAGE_BYTES + OFF_AH);  \
            __nv_bfloat16* AlS = (__nv_bfloat16*)(dsm + (buf) * STAGE_BYTES + OFF_AL);  \
            __nv_bfloat16* BhS = (__nv_bfloat16*)(dsm + (buf) * STAGE_BYTES + OFF_BH);  \
            __nv_bfloat16* BlS = (__nv_bfloat16*)(dsm + (buf) * STAGE_BYTES + OFF_BL);  \
            _Pragma("unroll")                                                           \
            for (int v = 0; v < 2; v++) {                                               \
                float vv[4] = {pa[v].x, pa[v].y, pa[v].z, pa[v].w};                     \
                uint16_t h[4], l[4];                                                    \
                _Pragma("unroll")                                                       \
                for (int i = 0; i < 4; i++) {                                           \
                    __nv_bfloat16 hb = __float2bfloat16(vv[i]);                         \
                    __nv_bfloat16 lb = __float2bfloat16(vv[i] - __bfloat162float(hb));  \
                    h[i] = __bfloat16_as_ushort(hb);                                    \
                    l[i] = __bfloat16_as_ushort(lb);                                    \
                }                                                                       \
                int r = v ? ar1 : ar0, c = v ? ac1 : ac0;                               \
                *(uint2*)(&AhS[r * ASTRIDE + c]) =                                      \
                    make_uint2(((uint32_t)h[1] << 16) | h[0], ((uint32_t)h[3] << 16) | h[2]); \
                *(uint2*)(&AlS[r * ASTRIDE + c]) =                                      \
                    make_uint2(((uint32_t)l[1] << 16) | l[0], ((uint32_t)l[3] << 16) | l[2]); \
            }                                                                           \
            _Pragma("unroll")                                                           \
            for (int v = 0; v < 4; v++) {                                               \
                float vv[4] = {pb[v].x, pb[v].y, pb[v].z, pb[v].w};                     \
                uint16_t h[4], l[4];                                                    \
                _Pragma("unroll")                                                       \
                for (int i = 0; i < 4; i++) {                                           \
                    __nv_bfloat16 hb = __float2bfloat16(vv[i]);                         \
                    __nv_bfloat16 lb = __float2bfloat16(vv[i] - __bfloat162float(hb));  \
                    h[i] = __bfloat16_as_ushort(hb);                                    \
                    l[i] = __bfloat16_as_ushort(lb);                                    \
                }                                                                       \
                *(uint2*)(&BhS[brr[v] * BSTRIDE + bcc[v]]) =                            \
                    make_uint2(((uint32_t)h[1] << 16) | h[0], ((uint32_t)h[3] << 16) | h[2]); \
                *(uint2*)(&BlS[brr[v] * BSTRIDE + bcc[v]]) =                            \
                    make_uint2(((uint32_t)l[1] << 16) | l[0], ((uint32_t)l[3] << 16) | l[2]); \
            }                                                                           \
        } while (0)

    // --- pipelined mainloop: 4 chunks of k=32, 3 passes each ---
    FETCH(0);
    CVT_STORE(0);
    __syncthreads();

    #pragma unroll
    for (int kc = 0; kc < 4; kc++) {
        const int cur = kc & 1;
        if (kc < 3) FETCH(kc + 1);

        const __nv_bfloat16* AhS = (const __nv_bfloat16*)(dsm + cur * STAGE_BYTES + OFF_AH);
        const __nv_bfloat16* AlS = (const __nv_bfloat16*)(dsm + cur * STAGE_BYTES + OFF_AL);
        const __nv_bfloat16* BhS = (const __nv_bfloat16*)(dsm + cur * STAGE_BYTES + OFF_BH);
        const __nv_bfloat16* BlS = (const __nv_bfloat16*)(dsm + cur * STAGE_BYTES + OFF_BL);

        #pragma unroll
        for (int pass = 0; pass < 3; pass++) {
            const __nv_bfloat16* Ap = (pass == 1) ? AlS : AhS;
            const __nv_bfloat16* Bp = (pass == 2) ? BlS : BhS;
            #pragma unroll
            for (int kk = 0; kk < 32; kk += 16) {
                wmma::fragment<wmma::matrix_a, 16, 16, 16, __nv_bfloat16, wmma::row_major> af[2];
                wmma::fragment<wmma::matrix_b, 16, 16, 16, __nv_bfloat16, wmma::row_major> bf[4];
                #pragma unroll
                for (int i = 0; i < 2; i++)
                    wmma::load_matrix_sync(af[i], Ap + (wm + i * 16) * ASTRIDE + kk, ASTRIDE);
                #pragma unroll
                for (int j = 0; j < 4; j++)
                    wmma::load_matrix_sync(bf[j], Bp + kk * BSTRIDE + wn + j * 16, BSTRIDE);
                #pragma unroll
                for (int i = 0; i < 2; i++)
                    #pragma unroll
                    for (int j = 0; j < 4; j++)
                        wmma::mma_sync(acc[i][j], af[i], bf[j], acc[i][j]);
            }
        }

        if (kc < 3) CVT_STORE(1 - cur);
        __syncthreads();
    }

    // --- epilogue: overlay Qs|Ks in dsm ---
    float* Qs = (float*)dsm;                       // 128 x QSTRIDE
    float* Ks = Qs + 128 * QSTRIDE;
    #pragma unroll
    for (int i = 0; i < 2; i++) {
        #pragma unroll
        for (int j = 0; j < 4; j++) {
            int n = wn + j * 16;
            float* t = (n < DIMP) ? (Qs + (wm + i * 16) * QSTRIDE + n)
                                  : (Ks + (wm + i * 16) * QSTRIDE + (n - DIMP));
            wmma::store_matrix_sync(t, acc[i][j], QSTRIDE, wmma::mem_row_major);
        }
    }
    if (tid < 128) maskS[tid] = mask[(size_t)bm + tid];
    __syncthreads();

    // K^T write: batch b, atom slot ns..ns+127. Coalesced stores per d-row.
    {
        const int b = mt >> 2, ns = (mt & 3) * 128;
        #pragma unroll
        for (int v = 0; v < 8; v++) {
            int f = v * 512 + tid;        // 0..4095
            int n = f & 127;
            int d4 = (f >> 7) * 4;        // 0..124
            float4 kv = *(float4*)(&Ks[n * QSTRIDE + d4]);
            g_Kt[b][d4 + 0][ns + n] = kv.x;
            g_Kt[b][d4 + 1][ns + n] = kv.y;
            g_Kt[b][d4 + 2][ns + n] = kv.z;
            g_Kt[b][d4 + 3][ns + n] = kv.w;
        }
    }

    // qsum partial: 4 row-groups of 32
    {
        const int d = tid & 127, h = tid >> 7;
        float acc_q = 0.0f;
        #pragma unroll 8
        for (int n = h * 32; n < h * 32 + 32; n++)
            acc_q += maskS[n] * Qs[n * QSTRIDE + d];
        partQ[h][d] = acc_q;
    }
    __syncthreads();
    if (tid < DIMP)
        g_qsum_part[mt][tid] = partQ[0][tid] + partQ[1][tid] + partQ[2][tid] + partQ[3][tid];

    // diag[n] = q[n] . k[n]  (16 warps x 8 rows)
    #pragma unroll
    for (int rr = 0; rr < 8; rr++) {
        const int n = warp * 8 + rr;
        const float4 q4 = *(const float4*)(&Qs[n * QSTRIDE + lane * 4]);
        const float4 k4 = *(const float4*)(&Ks[n * QSTRIDE + lane * 4]);
        float s = q4.x * k4.x + q4.y * k4.y + q4.z * k4.z + q4.w * k4.w;
        #pragma unroll
        for (int o = 16; o; o >>= 1) s += __shfl_down_sync(0xffffffffu, s, o);
        if (lane == 0) g_diag[(size_t)bm + n] = s;
    }
    #undef FETCH
    #undef CVT_STORE
}

// ---------------------------------------------------------------------------
// Block reductions (512 threads, 16 warps)
// ---------------------------------------------------------------------------
__device__ __forceinline__ float block_reduce_sum(float v, float* red) {
    int lane = threadIdx.x & 31, warp = threadIdx.x >> 5;
    #pragma unroll
    for (int o = 16; o; o >>= 1) v += __shfl_down_sync(0xffffffffu, v, o);
    if (lane == 0) red[warp] = v;
    __syncthreads();
    if (warp == 0) {
        v = (lane < 16) ? red[lane] : 0.0f;
        #pragma unroll
        for (int o = 8; o; o >>= 1) v += __shfl_down_sync(0xffffffffu, v, o);
        if (lane == 0) red[16] = v;
    }
    __syncthreads();
    float r = red[16];
    __syncthreads();
    return r;
}

__device__ __forceinline__ float block_reduce_max(float v, float* red) {
    int lane = threadIdx.x & 31, warp = threadIdx.x >> 5;
    #pragma unroll
    for (int o = 16; o; o >>= 1) v = fmaxf(v, __shfl_down_sync(0xffffffffu, v, o));
    if (lane == 0) red[warp] = v;
    __syncthreads();
    if (warp == 0) {
        v = (lane < 16) ? red[lane] : -INFINITY;
        #pragma unroll
        for (int o = 8; o; o >>= 1) v = fmaxf(v, __shfl_down_sync(0xffffffffu, v, o));
        if (lane == 0) red[16] = v;
    }
    __syncthreads();
    float r = red[16];
    __syncthreads();
    return r;
}

// ---------------------------------------------------------------------------
// attn_fused: grid BATCH, 512 threads. agg -> normalize -> softmax -> context.
// ---------------------------------------------------------------------------
__global__ __launch_bounds__(512)
void attn_fused_kernel(const float* __restrict__ mask, float* __restrict__ out) {
    const int b = blockIdx.x, tid = threadIdx.x;
    const int lane = tid & 31, warp = tid >> 5;
    __shared__ float qs[DIMP];
    __shared__ float aw[NATOM];
    __shared__ float red[17];

    if (tid < DIMP)
        qs[tid] = g_qsum_part[b * 4 + 0][tid] + g_qsum_part[b * 4 + 1][tid]
                + g_qsum_part[b * 4 + 2][tid] + g_qsum_part[b * 4 + 3][tid];
    __syncthreads();

    const float* __restrict__ Kt = &g_Kt[b][0][0];   // [128][512]

    // agg[n] = mask[n] * (k[n].qsum - diag[n]); thread-per-atom, coalesced
    float acc = 0.0f;
    #pragma unroll 8
    for (int d = 0; d < DIMP; d++)
        acc = fmaf(Kt[d * NATOM + tid], qs[d], acc);
    const float mv = mask[(size_t)b * NATOM + tid];
    const float v = mv * (acc - g_diag[(size_t)b * NATOM + tid]);

    // normalize over atoms, masked softmax
    const float total = block_reduce_sum(v * v, red);
    const float nrm = sqrtf(total);
    const float x = v / nrm + (1.0f - mv) * (-1e9f);
    const float mx = block_reduce_max(x, red);
    const float e = expf(x - mx);
    const float denom = block_reduce_sum(e, red);
    const float attn = e / denom;
    out[(size_t)b * NATOM + tid] = attn;
    aw[tid] = attn * mv;
    __syncthreads();

    // context[d] = sum_n aw[n] * Kt[d][n]; warp-per-d-row, contiguous rows
    #pragma unroll
    for (int r = 0; r < 8; r++) {
        const int d = warp * 8 + r;
        const float* row = Kt + d * NATOM;
        float s = 0.0f;
        #pragma unroll
        for (int j = 0; j < 4; j++) {
            const float4 k4 = *(const float4*)(row + j * 128 + lane * 4);
            const float4 a4 = *(const float4*)(&aw[j * 128 + lane * 4]);
            s += k4.x * a4.x + k4.y * a4.y + k4.z * a4.z + k4.w * a4.w;
        }
        #pragma unroll
        for (int o = 16; o; o >>= 1) s += __shfl_down_sync(0xffffffffu, s, o);
        if (lane == 0) out[(size_t)BATCH * NATOM + (size_t)b * DIMP + d] = s;
    }
}

// ---------------------------------------------------------------------------
extern "C" void kernel_launch(void* const* d_in, const int* in_sizes, int n_in,
                              void* d_out, int out_size) {
    const float* atom_query = (const float*)d_in[0];
    const float* mask       = (const float*)d_in[1];
    const float* Wq         = (const float*)d_in[2];
    const float* bq         = (const float*)d_in[3];
    const float* Wk         = (const float*)d_in[4];
    const float* bk         = (const float*)d_in[5];
    float* out = (float*)d_out;

    static int smem_set = 0;
    if (!smem_set) {
        cudaFuncSetAttribute(gemm_fused_kernel,
                             cudaFuncAttributeMaxDynamicSharedMemorySize, DSMEM_BYTES);
        smem_set = 1;
    }

    gemm_fused_kernel<<<NTILES, 512, DSMEM_BYTES>>>(atom_query, Wq, Wk, bq, bk, mask);
    attn_fused_kernel<<<BATCH, 512>>>(mask, out);
}